// round 2
// baseline (speedup 1.0000x reference)
#include <cuda_runtime.h>
#include <math.h>

#define SL   2048
#define DM   512
#define DI   1024
#define DS   16
#define DXZ  2048   // 2*DI
#define NSP  1056   // DI + 2*DS

// ---------------- scratch (static device globals; no allocation) ----------------
__device__ float g_X2[2 * SL * DM];       // [dir][l][DM]  (dir 1 is reversed input)
__device__ float g_xz[2 * SL * DXZ];      // in-proj output: x_ssm | z
__device__ float g_xconv[2 * SL * DI];    // post depthwise conv (pre-silu)
__device__ float g_sx[2 * SL * DI];       // silu(xconv)
__device__ float g_sp[2 * SL * NSP];      // xp-proj output: delta | B | C
__device__ float g_dt[2 * SL * DI];       // softplus(delta @ dtW + dtb)
__device__ float g_yz[2 * SL * DI];       // y * silu(z)
__device__ float g_cat[SL * 2 * DM];      // [l][ fwd(512) | bwd(512) ]

// ---------------- helpers ----------------
__device__ __forceinline__ float siluf(float v) {
    return v / (1.0f + __expf(-v));
}

// ---------------- prepare: fwd copy + bwd reversed copy ----------------
__global__ void k_prepare(const float* __restrict__ x) {
    int idx = blockIdx.x * blockDim.x + threadIdx.x;
    if (idx < SL * DM) {
        int l = idx / DM, d = idx % DM;
        float v = x[idx];
        g_X2[idx] = v;
        g_X2[SL * DM + (SL - 1 - l) * DM + d] = v;
    }
}

// ---------------- causal depthwise conv (K=4) + silu branch ----------------
__global__ void k_conv(const float* __restrict__ fcw, const float* __restrict__ fcb,
                       const float* __restrict__ bcw, const float* __restrict__ bcb) {
    int idx = blockIdx.x * blockDim.x + threadIdx.x;
    if (idx >= 2 * SL * DI) return;
    int b = idx / (SL * DI);
    int r = idx - b * SL * DI;
    int l = r / DI, d = r % DI;
    const float* cw = b ? bcw : fcw;
    const float* cb = b ? bcb : fcb;
    const float* xs = g_xz + (size_t)b * SL * DXZ; // x_ssm = first DI cols
    float acc = cb[d];
#pragma unroll
    for (int k = 0; k < 4; k++) {
        int ls = l + k - 3;
        if (ls >= 0) acc += cw[d * 4 + k] * xs[(size_t)ls * DXZ + d];
    }
    g_xconv[idx] = acc;
    g_sx[idx] = siluf(acc);
}

// ---------------- batched SGEMM: C = A @ W + bias, optional softplus, optional row-reverse store ----
// 128x128x8 tiles, 256 threads, 8x8 microtile.
struct GemmArgs {
    const float* A[2];
    const float* W[2];
    const float* bias[2];
    float*       C[2];
    int M, N, K, lda, ldw, ldc;
    int rev[2];
};

template <int EPI>  // 0 = none, 1 = softplus
__global__ void __launch_bounds__(256, 2) k_sgemm(GemmArgs ga) {
    const int bz = blockIdx.z;
    const float* __restrict__ A = ga.A[bz];
    const float* __restrict__ W = ga.W[bz];
    const float* __restrict__ bias = ga.bias[bz];
    float* __restrict__ C = ga.C[bz];
    const int M = ga.M, N = ga.N, K = ga.K;
    const int lda = ga.lda, ldw = ga.ldw, ldc = ga.ldc;
    const int rev = ga.rev[bz];

    __shared__ float As[8][128];
    __shared__ float Bs[8][128];

    const int t = threadIdx.x;
    const int m0 = blockIdx.y * 128;
    const int n0 = blockIdx.x * 128;

    // A loader: 128 rows x 8 k, float4 along K
    const int ar = t >> 1;            // 0..127
    const int ac = (t & 1) * 4;       // 0 or 4
    // B loader: 8 rows(k) x 128 n, float4 along N
    const int br = t >> 5;            // 0..7
    const int bc = (t & 31) * 4;      // 0..124

    const int tx = t & 15;            // n dir
    const int ty = t >> 4;            // m dir

    float acc[8][8];
#pragma unroll
    for (int i = 0; i < 8; i++)
#pragma unroll
        for (int j = 0; j < 8; j++) acc[i][j] = 0.0f;

    for (int kt = 0; kt < K; kt += 8) {
        float4 av = *reinterpret_cast<const float4*>(&A[(size_t)(m0 + ar) * lda + kt + ac]);
        As[ac + 0][ar] = av.x;
        As[ac + 1][ar] = av.y;
        As[ac + 2][ar] = av.z;
        As[ac + 3][ar] = av.w;

        float4 bv = make_float4(0.f, 0.f, 0.f, 0.f);
        if (n0 + bc < N)
            bv = *reinterpret_cast<const float4*>(&W[(size_t)(kt + br) * ldw + n0 + bc]);
        *reinterpret_cast<float4*>(&Bs[br][bc]) = bv;

        __syncthreads();
#pragma unroll
        for (int k = 0; k < 8; k++) {
            float4 a0 = *reinterpret_cast<const float4*>(&As[k][ty * 8]);
            float4 a1 = *reinterpret_cast<const float4*>(&As[k][ty * 8 + 4]);
            float4 b0 = *reinterpret_cast<const float4*>(&Bs[k][tx * 8]);
            float4 b1 = *reinterpret_cast<const float4*>(&Bs[k][tx * 8 + 4]);
            float af[8] = {a0.x, a0.y, a0.z, a0.w, a1.x, a1.y, a1.z, a1.w};
            float bf[8] = {b0.x, b0.y, b0.z, b0.w, b1.x, b1.y, b1.z, b1.w};
#pragma unroll
            for (int i = 0; i < 8; i++)
#pragma unroll
                for (int j = 0; j < 8; j++) acc[i][j] = fmaf(af[i], bf[j], acc[i][j]);
        }
        __syncthreads();
    }

#pragma unroll
    for (int i = 0; i < 8; i++) {
        int m = m0 + ty * 8 + i;
        int cr = rev ? (M - 1 - m) : m;
#pragma unroll
        for (int j = 0; j < 8; j++) {
            int n = n0 + tx * 8 + j;
            if (n < N) {
                float v = acc[i][j] + bias[n];
                if (EPI == 1) v = (v > 20.0f) ? v : log1pf(__expf(v));
                C[(size_t)cr * ldc + n] = v;
            }
        }
    }
}

// ---------------- selective scan + output gating ----------------
// One thread per (dir, channel, state); 16-lane shuffle reduce over states.
__global__ void k_scan(const float* __restrict__ A_log, const float* __restrict__ Dp) {
    const int b = blockIdx.y;
    const int tid = threadIdx.x;          // 256 = 16 channels x 16 states
    const int s = tid & 15;
    const int d = blockIdx.x * 16 + (tid >> 4);

    const float Ac = -__expf(A_log[d * DS + s]);
    const float Dv = Dp[d];

    const float* __restrict__ dtp = g_dt + (size_t)b * SL * DI;
    const float* __restrict__ xcp = g_xconv + (size_t)b * SL * DI;
    const float* __restrict__ spp = g_sp + (size_t)b * SL * NSP;
    const float* __restrict__ zp  = g_xz + (size_t)b * SL * DXZ + DI;
    float* __restrict__ yzp = g_yz + (size_t)b * SL * DI;

    float h = 0.0f;
    for (int l = 0; l < SL; l++) {
        float dt = dtp[(size_t)l * DI + d];
        float xv = xcp[(size_t)l * DI + d];
        float Bv = spp[(size_t)l * NSP + DI + s];
        float Cv = spp[(size_t)l * NSP + DI + DS + s];
        h = __expf(dt * Ac) * h + dt * Bv * xv;
        float p = h * Cv;
        p += __shfl_xor_sync(0xffffffffu, p, 8, 16);
        p += __shfl_xor_sync(0xffffffffu, p, 4, 16);
        p += __shfl_xor_sync(0xffffffffu, p, 2, 16);
        p += __shfl_xor_sync(0xffffffffu, p, 1, 16);
        if (s == 0) {
            float zv = zp[(size_t)l * DXZ + d];
            float y = p + Dv * xv;
            yzp[(size_t)l * DI + d] = y * siluf(zv);
        }
    }
}

// ---------------- host orchestration ----------------
extern "C" void kernel_launch(void* const* d_in, const int* in_sizes, int n_in,
                              void* d_out, int out_size) {
    const float* x = (const float*)d_in[0];
    // per-direction parameter blocks: fwd at 1..10, bwd at 11..20
    const float* inW[2]  = {(const float*)d_in[1],  (const float*)d_in[11]};
    const float* inb[2]  = {(const float*)d_in[2],  (const float*)d_in[12]};
    const float* cw[2]   = {(const float*)d_in[3],  (const float*)d_in[13]};
    const float* cb[2]   = {(const float*)d_in[4],  (const float*)d_in[14]};
    const float* xpW[2]  = {(const float*)d_in[5],  (const float*)d_in[15]};
    const float* xpb[2]  = {(const float*)d_in[6],  (const float*)d_in[16]};
    const float* dtW[2]  = {(const float*)d_in[7],  (const float*)d_in[17]};
    const float* dtb[2]  = {(const float*)d_in[8],  (const float*)d_in[18]};
    const float* outW[2] = {(const float*)d_in[9],  (const float*)d_in[19]};
    const float* outb[2] = {(const float*)d_in[10], (const float*)d_in[20]};
    const float* A_log   = (const float*)d_in[21];
    const float* Dp      = (const float*)d_in[22];
    const float* fuW     = (const float*)d_in[23];
    const float* fub     = (const float*)d_in[24];
    float* out = (float*)d_out;

    float *X2, *xz, *sx, *sp, *dtb_buf, *yz, *cat;
    cudaGetSymbolAddress((void**)&X2, g_X2);
    cudaGetSymbolAddress((void**)&xz, g_xz);
    cudaGetSymbolAddress((void**)&sx, g_sx);
    cudaGetSymbolAddress((void**)&sp, g_sp);
    cudaGetSymbolAddress((void**)&dtb_buf, g_dt);
    cudaGetSymbolAddress((void**)&yz, g_yz);
    cudaGetSymbolAddress((void**)&cat, g_cat);

    // 1. prepare inputs (fwd + reversed bwd)
    k_prepare<<<(SL * DM + 255) / 256, 256>>>(x);

    // 2. in-projection: xz = X2 @ inW + inb   [2048 x 2048, K=512]
    {
        GemmArgs ga;
        for (int b = 0; b < 2; b++) {
            ga.A[b] = X2 + (size_t)b * SL * DM;
            ga.W[b] = inW[b];
            ga.bias[b] = inb[b];
            ga.C[b] = xz + (size_t)b * SL * DXZ;
            ga.rev[b] = 0;
        }
        ga.M = SL; ga.N = DXZ; ga.K = DM; ga.lda = DM; ga.ldw = DXZ; ga.ldc = DXZ;
        k_sgemm<0><<<dim3((DXZ + 127) / 128, SL / 128, 2), 256>>>(ga);
    }

    // 3. causal depthwise conv + silu
    k_conv<<<(2 * SL * DI + 255) / 256, 256>>>(cw[0], cb[0], cw[1], cb[1]);

    // 4. xp-projection: sp = silu(xconv) @ xpW + xpb   [2048 x 1056, K=1024]
    {
        GemmArgs ga;
        for (int b = 0; b < 2; b++) {
            ga.A[b] = sx + (size_t)b * SL * DI;
            ga.W[b] = xpW[b];
            ga.bias[b] = xpb[b];
            ga.C[b] = sp + (size_t)b * SL * NSP;
            ga.rev[b] = 0;
        }
        ga.M = SL; ga.N = NSP; ga.K = DI; ga.lda = DI; ga.ldw = NSP; ga.ldc = NSP;
        k_sgemm<0><<<dim3((NSP + 127) / 128, SL / 128, 2), 256>>>(ga);
    }

    // 5. dt-projection + softplus: dt = softplus(delta @ dtW + dtb)  [2048 x 1024, K=1024]
    {
        GemmArgs ga;
        for (int b = 0; b < 2; b++) {
            ga.A[b] = sp + (size_t)b * SL * NSP;   // delta = first DI cols (lda = NSP)
            ga.W[b] = dtW[b];
            ga.bias[b] = dtb[b];
            ga.C[b] = dtb_buf + (size_t)b * SL * DI;
            ga.rev[b] = 0;
        }
        ga.M = SL; ga.N = DI; ga.K = DI; ga.lda = NSP; ga.ldw = DI; ga.ldc = DI;
        k_sgemm<1><<<dim3(DI / 128, SL / 128, 2), 256>>>(ga);
    }

    // 6. selective scan + gating: yz = (scan(...) + D*xconv) * silu(z)
    k_scan<<<dim3(DI / 16, 2), 256>>>(A_log, Dp);

    // 7. out-projection into concat buffer (bwd rows reversed back)
    {
        GemmArgs ga;
        for (int b = 0; b < 2; b++) {
            ga.A[b] = yz + (size_t)b * SL * DI;
            ga.W[b] = outW[b];
            ga.bias[b] = outb[b];
            ga.C[b] = cat + b * DM;                // column offset within [l][1024]
            ga.rev[b] = (b == 1);
        }
        ga.M = SL; ga.N = DM; ga.K = DI; ga.lda = DI; ga.ldw = DM; ga.ldc = 2 * DM;
        k_sgemm<0><<<dim3(DM / 128, SL / 128, 2), 256>>>(ga);
    }

    // 8. fusion: out = cat @ fusion_W + fusion_b   [2048 x 512, K=1024]
    {
        GemmArgs ga;
        ga.A[0] = ga.A[1] = cat;
        ga.W[0] = ga.W[1] = fuW;
        ga.bias[0] = ga.bias[1] = fub;
        ga.C[0] = ga.C[1] = out;
        ga.rev[0] = ga.rev[1] = 0;
        ga.M = SL; ga.N = DM; ga.K = 2 * DM; ga.lda = 2 * DM; ga.ldw = DM; ga.ldc = DM;
        k_sgemm<0><<<dim3(DM / 128, SL / 128, 1), 256>>>(ga);
    }
}

// round 4
// speedup vs baseline: 5.7697x; 5.7697x over previous
#include <cuda_runtime.h>
#include <cuda_bf16.h>
#include <math.h>
#include <stdint.h>

#define SL   2048
#define DM   512
#define DI   1024
#define DS   16
#define DXZ  2048   // 2*DI
#define NSP  1056   // DI + 2*DS
#define NSP_PAD 1152
#define NCH  16
#define CL   128    // SL / NCH

// ---------------- fp32 scratch ----------------
__device__ float g_xz[2 * SL * DXZ];      // in-proj output: x_ssm | z
__device__ float g_xconv[2 * SL * DI];    // post depthwise conv (pre-silu)
__device__ float g_sp[2 * SL * NSP];      // xp-proj output: delta | B | C
__device__ float g_dt[2 * SL * DI];       // softplus(delta @ dtW + dtb)
__device__ float g_cat[SL * 2 * DM];      // [l][ fwd | bwd ]
// scan chunk scratch
__device__ float g_dtsum[2 * DI * NCH];
__device__ float g_hpart[2 * DI * NCH * DS];
__device__ float g_hinit[2 * DI * NCH * DS];

// ---------------- bf16 hi/lo split activations (16B aligned for vector/cp.async) ----------------
__device__ __align__(16) __nv_bfloat16 g_X2h[2 * SL * DM], g_X2l[2 * SL * DM];
__device__ __align__(16) __nv_bfloat16 g_sxh[2 * SL * DI], g_sxl[2 * SL * DI];
__device__ __align__(16) __nv_bfloat16 g_dh [2 * SL * DI], g_dl [2 * SL * DI];
__device__ __align__(16) __nv_bfloat16 g_yzh[2 * SL * DI], g_yzl[2 * SL * DI];
__device__ __align__(16) __nv_bfloat16 g_cth[SL * 2 * DM], g_ctl[SL * 2 * DM];
// ---------------- bf16 hi/lo transposed weights [Npad][K] ----------------
__device__ __align__(16) __nv_bfloat16 g_inWh[2 * DXZ * DM],     g_inWl[2 * DXZ * DM];
__device__ __align__(16) __nv_bfloat16 g_xpWh[2 * NSP_PAD * DI], g_xpWl[2 * NSP_PAD * DI];
__device__ __align__(16) __nv_bfloat16 g_dtWh[2 * DI * DI],      g_dtWl[2 * DI * DI];
__device__ __align__(16) __nv_bfloat16 g_outWh[2 * DM * DI],     g_outWl[2 * DM * DI];
__device__ __align__(16) __nv_bfloat16 g_fuWh[DM * 2 * DM],      g_fuWl[DM * 2 * DM];

// ---------------- helpers ----------------
__device__ __forceinline__ float siluf(float v) { return v / (1.0f + __expf(-v)); }

__device__ __forceinline__ void split2(float x, __nv_bfloat16& h, __nv_bfloat16& l) {
    h = __float2bfloat16(x);
    l = __float2bfloat16(x - __bfloat162float(h));
}

__device__ __forceinline__ uint32_t smem_u32(const void* p) {
    uint32_t a;
    asm("{ .reg .u64 t; cvta.to.shared.u64 t, %1; cvt.u32.u64 %0, t; }" : "=r"(a) : "l"(p));
    return a;
}

__device__ __forceinline__ void cp16(uint32_t dst, const void* src) {
    asm volatile("cp.async.cg.shared.global [%0], [%1], 16;" :: "r"(dst), "l"(src));
}
__device__ __forceinline__ void cp_commit() {
    asm volatile("cp.async.commit_group;" ::: "memory");
}
__device__ __forceinline__ void cp_wait1() {
    asm volatile("cp.async.wait_group 1;" ::: "memory");
}

#define LDSM_X4(r0, r1, r2, r3, addr) \
    asm volatile("ldmatrix.sync.aligned.m8n8.x4.shared.b16 {%0,%1,%2,%3}, [%4];" \
                 : "=r"(r0), "=r"(r1), "=r"(r2), "=r"(r3) : "r"(addr))

#define MMA16816(d, a, b) \
    asm volatile("mma.sync.aligned.m16n8k16.row.col.f32.bf16.bf16.f32 " \
                 "{%0,%1,%2,%3}, {%4,%5,%6,%7}, {%8,%9}, {%0,%1,%2,%3};" \
                 : "+f"((d)[0]), "+f"((d)[1]), "+f"((d)[2]), "+f"((d)[3]) \
                 : "r"((a)[0]), "r"((a)[1]), "r"((a)[2]), "r"((a)[3]), \
                   "r"((b)[0]), "r"((b)[1]))

#define SWZ(o) ((o) ^ (((o) >> 3) & 0x70))

// ---------------- prepare: split x into fwd + reversed bwd bf16 halves ----------------
__global__ void k_prepare(const float* __restrict__ x) {
    int idx = blockIdx.x * blockDim.x + threadIdx.x;
    if (idx < SL * DM) {
        int l = idx / DM, d = idx % DM;
        __nv_bfloat16 h, lo;
        split2(x[idx], h, lo);
        g_X2h[idx] = h; g_X2l[idx] = lo;
        size_t r = (size_t)SL * DM + (size_t)(SL - 1 - l) * DM + d;
        g_X2h[r] = h; g_X2l[r] = lo;
    }
}

// ---------------- causal depthwise conv (K=4); writes fp32 xconv + split silu ----------------
__global__ void k_conv(const float* __restrict__ fcw, const float* __restrict__ fcb,
                       const float* __restrict__ bcw, const float* __restrict__ bcb) {
    int idx = blockIdx.x * blockDim.x + threadIdx.x;
    if (idx >= 2 * SL * DI) return;
    int b = idx / (SL * DI);
    int r = idx - b * SL * DI;
    int l = r / DI, d = r % DI;
    const float* cw = b ? bcw : fcw;
    const float* cb = b ? bcb : fcb;
    const float* xs = g_xz + (size_t)b * SL * DXZ;
    float acc = cb[d];
#pragma unroll
    for (int k = 0; k < 4; k++) {
        int ls = l + k - 3;
        if (ls >= 0) acc += cw[d * 4 + k] * xs[(size_t)ls * DXZ + d];
    }
    g_xconv[idx] = acc;
    __nv_bfloat16 h, lo;
    split2(siluf(acc), h, lo);
    g_sxh[idx] = h; g_sxl[idx] = lo;
}

// ---------------- generic activation split (strided source) ----------------
__global__ void k_splitA(const float* __restrict__ src, __nv_bfloat16* __restrict__ hi,
                         __nv_bfloat16* __restrict__ lo, int lda, int cols, int total) {
    int idx = blockIdx.x * blockDim.x + threadIdx.x;
    if (idx >= total) return;
    int r = idx / cols, c = idx - r * cols;
    __nv_bfloat16 h, l;
    split2(src[(size_t)r * lda + c], h, l);
    hi[idx] = h; lo[idx] = l;
}

// ---------------- weight transpose + split: W[K,N] -> Wt_{hi,lo}[Npad,K] ----------------
__global__ void k_wt(const float* __restrict__ W, __nv_bfloat16* __restrict__ hiT,
                     __nv_bfloat16* __restrict__ loT, int K, int N, int Npad) {
    __shared__ float s[32][33];
    int nb = blockIdx.x * 32, kb = blockIdx.y * 32;
    int tx = threadIdx.x, ty = threadIdx.y;
#pragma unroll
    for (int j = 0; j < 32; j += 8) {
        int k = kb + ty + j, n = nb + tx;
        s[ty + j][tx] = (n < N) ? W[(size_t)k * N + n] : 0.0f;
    }
    __syncthreads();
#pragma unroll
    for (int j = 0; j < 32; j += 8) {
        int n = nb + ty + j, k = kb + tx;
        float x = s[tx][ty + j];
        __nv_bfloat16 h, l;
        split2(x, h, l);
        hiT[(size_t)n * K + k] = h;
        loT[(size_t)n * K + k] = l;
    }
}

// ---------------- mma.sync bf16 3-term GEMM: C = A @ W^T + bias ----------------
// CTA tile 128x128, K-slab 64, 8 warps each 32(m)x64(n), 2-stage cp.async pipeline.
struct TArgs {
    const __nv_bfloat16 *Ah[2], *Al[2], *Bh[2], *Bl[2];
    const float* bias[2];
    float* C[2];
    int M, N, K, ldc;
    int rev[2];
};

#define TILE_B  16384      // 128 x 64 bf16
#define STAGE_B (4 * TILE_B)
#define GEMM_SMEM (2 * STAGE_B)

__device__ __forceinline__ void load_slab(uint32_t sdst,
    const __nv_bfloat16* Ah, const __nv_bfloat16* Al,
    const __nv_bfloat16* Bh, const __nv_bfloat16* Bl,
    int m0, int n0, int K, int kslab, int tid)
{
    const __nv_bfloat16* srcs[4] = {
        Ah + (size_t)m0 * K, Al + (size_t)m0 * K,
        Bh + (size_t)n0 * K, Bl + (size_t)n0 * K };
    const int kof = kslab * 64;
#pragma unroll
    for (int t = 0; t < 4; t++) {
#pragma unroll
        for (int i = 0; i < 4; i++) {
            int idx = tid + i * 256;
            int r = idx >> 3, c = idx & 7;
            uint32_t dst = sdst + t * TILE_B + SWZ(r * 128 + c * 16);
            cp16(dst, srcs[t] + (size_t)r * K + kof + c * 8);
        }
    }
}

template <int EPI>  // 0 none, 1 softplus
__global__ void __launch_bounds__(256, 1) k_mma_gemm(TArgs ga) {
    extern __shared__ __align__(1024) char smem[];
    const int bz = blockIdx.z;
    const __nv_bfloat16* __restrict__ Ah = ga.Ah[bz];
    const __nv_bfloat16* __restrict__ Al = ga.Al[bz];
    const __nv_bfloat16* __restrict__ Bh = ga.Bh[bz];
    const __nv_bfloat16* __restrict__ Bl = ga.Bl[bz];
    const float* __restrict__ bias = ga.bias[bz];
    float* __restrict__ C = ga.C[bz];
    const int K = ga.K, N = ga.N, ldc = ga.ldc, rev = ga.rev[bz];
    const int m0 = blockIdx.y * 128, n0 = blockIdx.x * 128;

    const int tid = threadIdx.x, wid = tid >> 5, lane = tid & 31;
    const int wm = (wid & 3) * 32;       // warp m offset in tile
    const int wn = (wid >> 2) * 64;      // warp n offset in tile
    const uint32_t sb = smem_u32(smem);

    float acc[2][8][4];
#pragma unroll
    for (int i = 0; i < 2; i++)
#pragma unroll
        for (int j = 0; j < 8; j++)
#pragma unroll
            for (int q = 0; q < 4; q++) acc[i][j][q] = 0.0f;

    const int nslab = K / 64;

    // prologue: slab 0 -> stage 0, slab 1 -> stage 1 (dummy commits keep group count constant)
    load_slab(sb, Ah, Al, Bh, Bl, m0, n0, K, 0, tid);
    cp_commit();
    if (nslab > 1) load_slab(sb + STAGE_B, Ah, Al, Bh, Bl, m0, n0, K, 1, tid);
    cp_commit();

    // precomputed ldmatrix lane offsets (within a tile, pre-swizzle row/col parts)
    const int a_row = (lane & 15);               // + wm + mi*16
    const int a_kc  = (lane >> 4) * 16;          // byte chunk within kstep
    const int b_row = (lane & 7) + ((lane >> 4) << 3);   // + wn + jj*16
    const int b_kc  = ((lane >> 3) & 1) * 16;

    for (int sl = 0; sl < nslab; sl++) {
        cp_wait1();
        __syncthreads();
        const uint32_t st = sb + (sl & 1) * STAGE_B;
        const uint32_t stAh = st, stAl = st + TILE_B, stBh = st + 2 * TILE_B, stBl = st + 3 * TILE_B;

#pragma unroll
        for (int ks = 0; ks < 4; ks++) {
            uint32_t ah[2][4], al[2][4];
#pragma unroll
            for (int mi = 0; mi < 2; mi++) {
                uint32_t off = SWZ((wm + mi * 16 + a_row) * 128 + ks * 32 + a_kc);
                LDSM_X4(ah[mi][0], ah[mi][1], ah[mi][2], ah[mi][3], stAh + off);
                LDSM_X4(al[mi][0], al[mi][1], al[mi][2], al[mi][3], stAl + off);
            }
            uint32_t bh[8][2], bl[8][2];
#pragma unroll
            for (int jj = 0; jj < 4; jj++) {
                uint32_t off = SWZ((wn + jj * 16 + b_row) * 128 + ks * 32 + b_kc);
                uint32_t r0, r1, r2, r3;
                LDSM_X4(r0, r1, r2, r3, stBh + off);
                bh[jj * 2][0] = r0; bh[jj * 2][1] = r1;
                bh[jj * 2 + 1][0] = r2; bh[jj * 2 + 1][1] = r3;
                LDSM_X4(r0, r1, r2, r3, stBl + off);
                bl[jj * 2][0] = r0; bl[jj * 2][1] = r1;
                bl[jj * 2 + 1][0] = r2; bl[jj * 2 + 1][1] = r3;
            }
#pragma unroll
            for (int mi = 0; mi < 2; mi++)
#pragma unroll
                for (int nj = 0; nj < 8; nj++) {
                    MMA16816(acc[mi][nj], ah[mi], bh[nj]);
                    MMA16816(acc[mi][nj], ah[mi], bl[nj]);
                    MMA16816(acc[mi][nj], al[mi], bh[nj]);
                }
        }
        __syncthreads();
        if (sl + 2 < nslab)
            load_slab(sb + (sl & 1) * STAGE_B, Ah, Al, Bh, Bl, m0, n0, K, sl + 2, tid);
        cp_commit();
    }

    // epilogue: direct global stores with bias / softplus / row-reverse
    const int gid = lane >> 2, tig = lane & 3;
#pragma unroll
    for (int mi = 0; mi < 2; mi++) {
        int mb = m0 + wm + mi * 16 + gid;
        int r1 = rev ? (ga.M - 1 - mb) : mb;
        int r2 = rev ? (ga.M - 1 - (mb + 8)) : (mb + 8);
#pragma unroll
        for (int nj = 0; nj < 8; nj++) {
            int nc = n0 + wn + nj * 8 + tig * 2;
            if (nc < N) {
                float b0 = bias[nc], b1 = bias[nc + 1];
                float v0 = acc[mi][nj][0] + b0;
                float v1 = acc[mi][nj][1] + b1;
                float v2 = acc[mi][nj][2] + b0;
                float v3 = acc[mi][nj][3] + b1;
                if (EPI == 1) {
                    v0 = (v0 > 20.0f) ? v0 : log1pf(__expf(v0));
                    v1 = (v1 > 20.0f) ? v1 : log1pf(__expf(v1));
                    v2 = (v2 > 20.0f) ? v2 : log1pf(__expf(v2));
                    v3 = (v3 > 20.0f) ? v3 : log1pf(__expf(v3));
                }
                *(float2*)&C[(size_t)r1 * ldc + nc] = make_float2(v0, v1);
                *(float2*)&C[(size_t)r2 * ldc + nc] = make_float2(v2, v3);
            }
        }
    }
}

// ---------------- chunked selective scan ----------------
// phase A: per (dir, d, chunk) local recurrence from h=0; stores h_part[16] + sum(dt)
__global__ void k_scanA(const float* __restrict__ A_log) {
    __shared__ float sB[CL][DS];
    const int b = blockIdx.z, ch = blockIdx.y;
    const int d = blockIdx.x * 128 + threadIdx.x;
    const float* __restrict__ spp = g_sp + (size_t)b * SL * NSP;
    for (int i = threadIdx.x; i < CL * DS; i += 128) {
        int l = i >> 4, s = i & 15;
        sB[l][s] = spp[(size_t)(ch * CL + l) * NSP + DI + s];
    }
    __syncthreads();
    float Ac[DS];
#pragma unroll
    for (int s = 0; s < DS; s++) Ac[s] = -__expf(A_log[d * DS + s]);
    float h[DS];
#pragma unroll
    for (int s = 0; s < DS; s++) h[s] = 0.0f;
    float dts = 0.0f;
    const float* __restrict__ dtp = g_dt + (size_t)b * SL * DI;
    const float* __restrict__ xcp = g_xconv + (size_t)b * SL * DI;
    for (int l = 0; l < CL; l++) {
        int gl = ch * CL + l;
        float dt = dtp[(size_t)gl * DI + d];
        float xv = xcp[(size_t)gl * DI + d];
        dts += dt;
        float du = dt * xv;
#pragma unroll
        for (int s = 0; s < DS; s++) h[s] = __expf(dt * Ac[s]) * h[s] + du * sB[l][s];
    }
    size_t base = ((size_t)(b * DI + d) * NCH + ch) * DS;
#pragma unroll
    for (int s = 0; s < DS; s++) g_hpart[base + s] = h[s];
    g_dtsum[(size_t)(b * DI + d) * NCH + ch] = dts;
}

// phase B: sequential combine over chunks; exp(Ac*sum_dt) is the chunk A-aggregate
__global__ void k_scanB(const float* __restrict__ A_log) {
    int idx = blockIdx.x * 256 + threadIdx.x;   // 2*DI*DS
    if (idx >= 2 * DI * DS) return;
    int s = idx & 15;
    int d = (idx >> 4) & (DI - 1);
    int b = idx >> 14;
    float Ac = -__expf(A_log[d * DS + s]);
    float h = 0.0f;
    size_t bd = (size_t)(b * DI + d) * NCH;
    for (int ch = 0; ch < NCH; ch++) {
        g_hinit[(bd + ch) * DS + s] = h;
        h = __expf(g_dtsum[bd + ch] * Ac) * h + g_hpart[(bd + ch) * DS + s];
    }
}

// phase C: replay with correct h_init, emit gated output split to bf16
__global__ void k_scanC(const float* __restrict__ A_log, const float* __restrict__ Dp) {
    __shared__ float sB[CL][DS];
    __shared__ float sC[CL][DS];
    const int b = blockIdx.z, ch = blockIdx.y;
    const int d = blockIdx.x * 128 + threadIdx.x;
    const float* __restrict__ spp = g_sp + (size_t)b * SL * NSP;
    for (int i = threadIdx.x; i < CL * DS; i += 128) {
        int l = i >> 4, s = i & 15;
        sB[l][s] = spp[(size_t)(ch * CL + l) * NSP + DI + s];
        sC[l][s] = spp[(size_t)(ch * CL + l) * NSP + DI + DS + s];
    }
    __syncthreads();
    float Ac[DS];
#pragma unroll
    for (int s = 0; s < DS; s++) Ac[s] = -__expf(A_log[d * DS + s]);
    float h[DS];
    size_t hbase = ((size_t)(b * DI + d) * NCH + ch) * DS;
#pragma unroll
    for (int s = 0; s < DS; s++) h[s] = g_hinit[hbase + s];
    const float Dv = Dp[d];
    const float* __restrict__ dtp = g_dt + (size_t)b * SL * DI;
    const float* __restrict__ xcp = g_xconv + (size_t)b * SL * DI;
    const float* __restrict__ zp  = g_xz + (size_t)b * SL * DXZ + DI;
    __nv_bfloat16* __restrict__ yh = g_yzh + (size_t)b * SL * DI;
    __nv_bfloat16* __restrict__ yl = g_yzl + (size_t)b * SL * DI;
    for (int l = 0; l < CL; l++) {
        int gl = ch * CL + l;
        float dt = dtp[(size_t)gl * DI + d];
        float xv = xcp[(size_t)gl * DI + d];
        float du = dt * xv;
        float y = Dv * xv;
#pragma unroll
        for (int s = 0; s < DS; s++) {
            h[s] = __expf(dt * Ac[s]) * h[s] + du * sB[l][s];
            y += h[s] * sC[l][s];
        }
        float zv = zp[(size_t)gl * DXZ + d];
        float o = y * siluf(zv);
        __nv_bfloat16 oh, ol;
        split2(o, oh, ol);
        yh[(size_t)gl * DI + d] = oh;
        yl[(size_t)gl * DI + d] = ol;
    }
}

// ---------------- host orchestration ----------------
extern "C" void kernel_launch(void* const* d_in, const int* in_sizes, int n_in,
                              void* d_out, int out_size) {
    const float* x = (const float*)d_in[0];
    const float* inW[2]  = {(const float*)d_in[1],  (const float*)d_in[11]};
    const float* inb[2]  = {(const float*)d_in[2],  (const float*)d_in[12]};
    const float* cw[2]   = {(const float*)d_in[3],  (const float*)d_in[13]};
    const float* cb[2]   = {(const float*)d_in[4],  (const float*)d_in[14]};
    const float* xpW[2]  = {(const float*)d_in[5],  (const float*)d_in[15]};
    const float* xpb[2]  = {(const float*)d_in[6],  (const float*)d_in[16]};
    const float* dtW[2]  = {(const float*)d_in[7],  (const float*)d_in[17]};
    const float* dtb[2]  = {(const float*)d_in[8],  (const float*)d_in[18]};
    const float* outW[2] = {(const float*)d_in[9],  (const float*)d_in[19]};
    const float* outb[2] = {(const float*)d_in[10], (const float*)d_in[20]};
    const float* A_log   = (const float*)d_in[21];
    const float* Dp      = (const float*)d_in[22];
    const float* fuW     = (const float*)d_in[23];
    const float* fub     = (const float*)d_in[24];
    float* out = (float*)d_out;

    cudaFuncSetAttribute(k_mma_gemm<0>, cudaFuncAttributeMaxDynamicSharedMemorySize, GEMM_SMEM);
    cudaFuncSetAttribute(k_mma_gemm<1>, cudaFuncAttributeMaxDynamicSharedMemorySize, GEMM_SMEM);

    float *xz, *sp, *dtbuf, *cat;
    __nv_bfloat16 *X2h, *X2l, *sxh, *sxl, *dh, *dl, *yzh, *yzl, *cth, *ctl;
    __nv_bfloat16 *inWh, *inWl, *xpWh, *xpWl, *dtWh, *dtWl, *outWh, *outWl, *fuWh, *fuWl;
    cudaGetSymbolAddress((void**)&xz, g_xz);
    cudaGetSymbolAddress((void**)&sp, g_sp);
    cudaGetSymbolAddress((void**)&dtbuf, g_dt);
    cudaGetSymbolAddress((void**)&cat, g_cat);
    cudaGetSymbolAddress((void**)&X2h, g_X2h);  cudaGetSymbolAddress((void**)&X2l, g_X2l);
    cudaGetSymbolAddress((void**)&sxh, g_sxh);  cudaGetSymbolAddress((void**)&sxl, g_sxl);
    cudaGetSymbolAddress((void**)&dh, g_dh);    cudaGetSymbolAddress((void**)&dl, g_dl);
    cudaGetSymbolAddress((void**)&yzh, g_yzh);  cudaGetSymbolAddress((void**)&yzl, g_yzl);
    cudaGetSymbolAddress((void**)&cth, g_cth);  cudaGetSymbolAddress((void**)&ctl, g_ctl);
    cudaGetSymbolAddress((void**)&inWh, g_inWh);   cudaGetSymbolAddress((void**)&inWl, g_inWl);
    cudaGetSymbolAddress((void**)&xpWh, g_xpWh);   cudaGetSymbolAddress((void**)&xpWl, g_xpWl);
    cudaGetSymbolAddress((void**)&dtWh, g_dtWh);   cudaGetSymbolAddress((void**)&dtWl, g_dtWl);
    cudaGetSymbolAddress((void**)&outWh, g_outWh); cudaGetSymbolAddress((void**)&outWl, g_outWl);
    cudaGetSymbolAddress((void**)&fuWh, g_fuWh);   cudaGetSymbolAddress((void**)&fuWl, g_fuWl);

    // 0. weight transpose + split
    dim3 tb(32, 8);
    for (int b = 0; b < 2; b++) {
        k_wt<<<dim3(DXZ / 32, DM / 32), tb>>>(inW[b],  inWh + (size_t)b * DXZ * DM,     inWl + (size_t)b * DXZ * DM,     DM, DXZ, DXZ);
        k_wt<<<dim3(NSP_PAD / 32, DI / 32), tb>>>(xpW[b], xpWh + (size_t)b * NSP_PAD * DI, xpWl + (size_t)b * NSP_PAD * DI, DI, NSP, NSP_PAD);
        k_wt<<<dim3(DI / 32, DI / 32), tb>>>(dtW[b],  dtWh + (size_t)b * DI * DI,      dtWl + (size_t)b * DI * DI,      DI, DI, DI);
        k_wt<<<dim3(DM / 32, DI / 32), tb>>>(outW[b], outWh + (size_t)b * DM * DI,     outWl + (size_t)b * DM * DI,     DI, DM, DM);
    }
    k_wt<<<dim3(DM / 32, (2 * DM) / 32), tb>>>(fuW, fuWh, fuWl, 2 * DM, DM, DM);

    // 1. prepare inputs (fwd + reversed bwd), split to bf16
    k_prepare<<<(SL * DM + 255) / 256, 256>>>(x);

    // 2. in-projection: [2048 x 2048], K=512
    {
        TArgs ga;
        for (int b = 0; b < 2; b++) {
            ga.Ah[b] = X2h + (size_t)b * SL * DM;  ga.Al[b] = X2l + (size_t)b * SL * DM;
            ga.Bh[b] = inWh + (size_t)b * DXZ * DM; ga.Bl[b] = inWl + (size_t)b * DXZ * DM;
            ga.bias[b] = inb[b];
            ga.C[b] = xz + (size_t)b * SL * DXZ;
            ga.rev[b] = 0;
        }
        ga.M = SL; ga.N = DXZ; ga.K = DM; ga.ldc = DXZ;
        k_mma_gemm<0><<<dim3(DXZ / 128, SL / 128, 2), 256, GEMM_SMEM>>>(ga);
    }

    // 3. depthwise conv + silu split
    k_conv<<<(2 * SL * DI + 255) / 256, 256>>>(cw[0], cb[0], cw[1], cb[1]);

    // 4. xp-projection: [2048 x 1056], K=1024
    {
        TArgs ga;
        for (int b = 0; b < 2; b++) {
            ga.Ah[b] = sxh + (size_t)b * SL * DI;  ga.Al[b] = sxl + (size_t)b * SL * DI;
            ga.Bh[b] = xpWh + (size_t)b * NSP_PAD * DI; ga.Bl[b] = xpWl + (size_t)b * NSP_PAD * DI;
            ga.bias[b] = xpb[b];
            ga.C[b] = sp + (size_t)b * SL * NSP;
            ga.rev[b] = 0;
        }
        ga.M = SL; ga.N = NSP; ga.K = DI; ga.ldc = NSP;
        k_mma_gemm<0><<<dim3(NSP_PAD / 128, SL / 128, 2), 256, GEMM_SMEM>>>(ga);
    }

    // 5. split delta (strided view of sp)
    k_splitA<<<(2 * SL * DI + 255) / 256, 256>>>(sp, dh, dl, NSP, DI, 2 * SL * DI);

    // 6. dt-projection + softplus: [2048 x 1024], K=1024
    {
        TArgs ga;
        for (int b = 0; b < 2; b++) {
            ga.Ah[b] = dh + (size_t)b * SL * DI;  ga.Al[b] = dl + (size_t)b * SL * DI;
            ga.Bh[b] = dtWh + (size_t)b * DI * DI; ga.Bl[b] = dtWl + (size_t)b * DI * DI;
            ga.bias[b] = dtb[b];
            ga.C[b] = dtbuf + (size_t)b * SL * DI;
            ga.rev[b] = 0;
        }
        ga.M = SL; ga.N = DI; ga.K = DI; ga.ldc = DI;
        k_mma_gemm<1><<<dim3(DI / 128, SL / 128, 2), 256, GEMM_SMEM>>>(ga);
    }

    // 7. chunked selective scan
    k_scanA<<<dim3(DI / 128, NCH, 2), 128>>>(A_log);
    k_scanB<<<(2 * DI * DS + 255) / 256, 256>>>(A_log);
    k_scanC<<<dim3(DI / 128, NCH, 2), 128>>>(A_log, Dp);

    // 8. out-projection into concat buffer (bwd rows reversed back)
    {
        TArgs ga;
        for (int b = 0; b < 2; b++) {
            ga.Ah[b] = yzh + (size_t)b * SL * DI;  ga.Al[b] = yzl + (size_t)b * SL * DI;
            ga.Bh[b] = outWh + (size_t)b * DM * DI; ga.Bl[b] = outWl + (size_t)b * DM * DI;
            ga.bias[b] = outb[b];
            ga.C[b] = cat + b * DM;
            ga.rev[b] = (b == 1);
        }
        ga.M = SL; ga.N = DM; ga.K = DI; ga.ldc = 2 * DM;
        k_mma_gemm<0><<<dim3(DM / 128, SL / 128, 2), 256, GEMM_SMEM>>>(ga);
    }

    // 9. split cat
    k_splitA<<<(SL * 2 * DM + 255) / 256, 256>>>(cat, cth, ctl, 2 * DM, 2 * DM, SL * 2 * DM);

    // 10. fusion: [2048 x 512], K=1024
    {
        TArgs ga;
        ga.Ah[0] = ga.Ah[1] = cth; ga.Al[0] = ga.Al[1] = ctl;
        ga.Bh[0] = ga.Bh[1] = fuWh; ga.Bl[0] = ga.Bl[1] = fuWl;
        ga.bias[0] = ga.bias[1] = fub;
        ga.C[0] = ga.C[1] = out;
        ga.rev[0] = ga.rev[1] = 0;
        ga.M = SL; ga.N = DM; ga.K = 2 * DM; ga.ldc = DM;
        k_mma_gemm<0><<<dim3(DM / 128, SL / 128, 1), 256, GEMM_SMEM>>>(ga);
    }
}